// round 10
// baseline (speedup 1.0000x reference)
#include <cuda_runtime.h>

// C[b,g] = softor_s( softand_l( x[b, I[g,s,l]] ) ),  gamma = 1e-3
// B=64, G=2048, S=32, L=8
//
// Scaled domain: w = -x * KINV  (KINV = 1/(gamma*ln2))
//   softand':  mW = max_l w,  sum = sum_l exp2(w_l - mW),  aw = mW + lg2(sum)
//   softor' :  Mw = min_s aw,  S = sum_s exp2(Mw - aw_s)
//              C  = (lg2(S) - Mw) * gamma*ln2
// Inner loop uses packed f32x2 FMA/ADD (sm_100+); max stays scalar (no
// packed f32 min/max exists in PTX).

#define NB 64
#define NG 2048
#define NS 32
#define NL 8
#define NCHUNK 8              // s-dimension split across 8 warps
#define SPER (NS / NCHUNK)    // 4 s-values per chunk
#define NTHR (NCHUNK * 32)    // 256 threads

#define KINV 1442.6950408889634f
#define GLN2 0.0006931471805599453f

typedef unsigned long long u64;

// Transposed, negated, scaled x: w[g][b] = -x[b][g] * KINV.
__device__ float g_w[NG * NB];

// Tiled transpose 64x2048 -> 2048x64, coalesced both sides; fuses -x*KINV.
__global__ void transpose_kernel(const float* __restrict__ x) {
    __shared__ float tile[32][33];
    const int gx = blockIdx.x * 32;
    const int bx = blockIdx.y * 32;
    const int tx = threadIdx.x;
    const int ty = threadIdx.y;
#pragma unroll
    for (int i = 0; i < 32; i += 8)
        tile[ty + i][tx] = x[(bx + ty + i) * NG + gx + tx] * (-KINV);
    __syncthreads();
#pragma unroll
    for (int i = 0; i < 32; i += 8)
        g_w[(gx + ty + i) * NB + bx + tx] = tile[tx][ty + i];
#if __CUDA_ARCH__ >= 900
    // Trigger AFTER the g_w stores: only writes before the trigger are
    // guaranteed visible at the dependent grid's cudaGridDependencySynchronize.
    cudaTriggerProgrammaticLaunchCompletion();
#endif
}

__device__ __forceinline__ float ex2_approx(float t) {
    float r;
    asm("ex2.approx.ftz.f32 %0, %1;" : "=f"(r) : "f"(t));
    return r;
}
__device__ __forceinline__ float lg2_approx(float t) {
    float r;
    asm("lg2.approx.f32 %0, %1;" : "=f"(r) : "f"(t));
    return r;
}

// ---- packed f32x2 helpers (sm_100+: add/sub/mul/fma only) ----
__device__ __forceinline__ u64 fadd2(u64 a, u64 b) {
    u64 r; asm("add.rn.f32x2 %0, %1, %2;" : "=l"(r) : "l"(a), "l"(b)); return r;
}
// d = a*b + c, packed
__device__ __forceinline__ u64 ffma2(u64 a, u64 b, u64 c) {
    u64 r; asm("fma.rn.f32x2 %0, %1, %2, %3;" : "=l"(r) : "l"(a), "l"(b), "l"(c));
    return r;
}
__device__ __forceinline__ void unpack2(u64 t, float& lo, float& hi) {
    asm("mov.b64 {%0, %1}, %2;" : "=f"(lo), "=f"(hi) : "l"(t));
}
__device__ __forceinline__ u64 pack2(float lo, float hi) {
    u64 r; asm("mov.b64 %0, {%1, %2};" : "=l"(r) : "f"(lo), "f"(hi)); return r;
}
// ex2 on both halves (MUFU is fp32-only; mov.b64 on reg pairs elides).
__device__ __forceinline__ u64 ex2pair(u64 t) {
    float lo, hi;
    unpack2(t, lo, hi);
    return pack2(ex2_approx(lo), ex2_approx(hi));
}

// One block (256 threads) per g; min 8 blocks/SM.
__global__ __launch_bounds__(NTHR, 8) void clause_kernel(
    const int* __restrict__ I,  // [NG, NS, NL] int32
    float* __restrict__ out)    // [NB, NG]
{
    const int g = blockIdx.x;
    const int tid = threadIdx.x;
    const int lane = tid & 31;
    const int chunk = tid >> 5;

    __shared__ int soff[NS * NL];          // pre-shifted byte offsets
    __shared__ float2 pM2[NCHUNK][NB / 2]; // partial min(aw) per chunk
    __shared__ float2 pS2[NCHUNK][NB / 2]; // partial sum-of-exp per chunk

    // Prologue: independent of g_w — overlaps with the transpose under PDL.
    if (tid < NS * NL / 4) {
        int4 r = ((const int4*)(I + g * (NS * NL)))[tid];
        r.x = (r.x & (NG - 1)) << 8;   // *256 bytes = row stride in bytes
        r.y = (r.y & (NG - 1)) << 8;
        r.z = (r.z & (NG - 1)) << 8;
        r.w = (r.w & (NG - 1)) << 8;
        ((int4*)soff)[tid] = r;
    }
    __syncthreads();

#if __CUDA_ARCH__ >= 900
    cudaGridDependencySynchronize();
#endif

    const char* lanebase = (const char*)g_w + lane * 8;
    const int4* __restrict__ soff4 = (const int4*)soff;
    const u64 NEG1x2 = 0xBF800000BF800000ull;  // packed (-1.0f, -1.0f)

    float awx[SPER], awy[SPER];

#pragma unroll
    for (int si = 0; si < SPER; si++) {
        const int s = chunk * SPER + si;
        const int4 o0 = soff4[s * 2 + 0];
        const int4 o1 = soff4[s * 2 + 1];

        u64 w0 = *(const u64*)(lanebase + o0.x);
        u64 w1 = *(const u64*)(lanebase + o0.y);
        u64 w2 = *(const u64*)(lanebase + o0.z);
        u64 w3 = *(const u64*)(lanebase + o0.w);
        u64 w4 = *(const u64*)(lanebase + o1.x);
        u64 w5 = *(const u64*)(lanebase + o1.y);
        u64 w6 = *(const u64*)(lanebase + o1.z);
        u64 w7 = *(const u64*)(lanebase + o1.w);

        // Scalar max trees on the halves (mov.b64 unpacks are free).
        float x0, y0, x1, y1, x2, y2, x3, y3, x4, y4, x5, y5, x6, y6, x7, y7;
        unpack2(w0, x0, y0); unpack2(w1, x1, y1);
        unpack2(w2, x2, y2); unpack2(w3, x3, y3);
        unpack2(w4, x4, y4); unpack2(w5, x5, y5);
        unpack2(w6, x6, y6); unpack2(w7, x7, y7);
        float mx = fmaxf(fmaxf(fmaxf(x0, x1), fmaxf(x2, x3)),
                         fmaxf(fmaxf(x4, x5), fmaxf(x6, x7)));
        float my = fmaxf(fmaxf(fmaxf(y0, y1), fmaxf(y2, y3)),
                         fmaxf(fmaxf(y4, y5), fmaxf(y6, y7)));
        u64 m = pack2(mx, my);

        // Packed diff via FMA2 (w - m == fma(m, -1, w), bitwise same as sub.rn),
        // MUFU ex2 on halves, packed sum tree.
        u64 e0 = ex2pair(ffma2(m, NEG1x2, w0));
        u64 e1 = ex2pair(ffma2(m, NEG1x2, w1));
        u64 e2 = ex2pair(ffma2(m, NEG1x2, w2));
        u64 e3 = ex2pair(ffma2(m, NEG1x2, w3));
        u64 e4 = ex2pair(ffma2(m, NEG1x2, w4));
        u64 e5 = ex2pair(ffma2(m, NEG1x2, w5));
        u64 e6 = ex2pair(ffma2(m, NEG1x2, w6));
        u64 e7 = ex2pair(ffma2(m, NEG1x2, w7));
        u64 ssum = fadd2(fadd2(fadd2(e0, e1), fadd2(e2, e3)),
                         fadd2(fadd2(e4, e5), fadd2(e6, e7)));

        float sx, sy;
        unpack2(ssum, sx, sy);
        awx[si] = mx + lg2_approx(sx);
        awy[si] = my + lg2_approx(sy);
    }

    // Partial softor over this chunk's SPER aw values (min in w-domain).
    float Mwx = fminf(fminf(awx[0], awx[1]), fminf(awx[2], awx[3]));
    float Mwy = fminf(fminf(awy[0], awy[1]), fminf(awy[2], awy[3]));
    float Sx = ex2_approx(Mwx - awx[0]) + ex2_approx(Mwx - awx[1])
             + ex2_approx(Mwx - awx[2]) + ex2_approx(Mwx - awx[3]);
    float Sy = ex2_approx(Mwy - awy[0]) + ex2_approx(Mwy - awy[1])
             + ex2_approx(Mwy - awy[2]) + ex2_approx(Mwy - awy[3]);

    pM2[chunk][lane] = make_float2(Mwx, Mwy);
    pS2[chunk][lane] = make_float2(Sx, Sy);
    __syncthreads();

    // First 64 threads: merge NCHUNK partials per b and write out.
    if (tid < NB) {
        const int b = tid;
        const float* pM = (const float*)pM2;  // [NCHUNK][NB]
        const float* pS = (const float*)pS2;
        float Mw = pM[b];
#pragma unroll
        for (int c = 1; c < NCHUNK; c++) Mw = fminf(Mw, pM[c * NB + b]);
        float S = 0.0f;
#pragma unroll
        for (int c = 0; c < NCHUNK; c++)
            S = fmaf(pS[c * NB + b], ex2_approx(Mw - pM[c * NB + b]), S);
        out[b * NG + g] = (lg2_approx(S) - Mw) * GLN2;
    }
}

extern "C" void kernel_launch(void* const* d_in, const int* in_sizes, int n_in,
                              void* d_out, int out_size) {
    // Identify inputs by element count:
    //   x:  64*2048   = 131072 float32
    //   I:  2048*32*8 = 524288 int32
    const float* x = nullptr;
    const int* I = nullptr;
    for (int i = 0; i < n_in; i++) {
        if (in_sizes[i] == NB * NG)           x = (const float*)d_in[i];
        else if (in_sizes[i] == NG * NS * NL) I = (const int*)d_in[i];
    }

    float* out = (float*)d_out;  // [64, 2048] fp32

    dim3 tgrid(NG / 32, NB / 32);
    dim3 tblock(32, 8);
    transpose_kernel<<<tgrid, tblock>>>(x);

    // PDL: clause_kernel launches early; it gates on transpose completion
    // (trigger placed after the g_w stores) before touching g_w.
    cudaLaunchConfig_t cfg = {};
    cfg.gridDim = dim3(NG);
    cfg.blockDim = dim3(NTHR);
    cfg.dynamicSmemBytes = 0;
    cfg.stream = 0;
    cudaLaunchAttribute attr[1];
    attr[0].id = cudaLaunchAttributeProgrammaticStreamSerialization;
    attr[0].val.programmaticStreamSerializationAllowed = 1;
    cfg.attrs = attr;
    cfg.numAttrs = 1;
    cudaLaunchKernelEx(&cfg, clause_kernel, I, (float*)d_out);
}

// round 11
// speedup vs baseline: 1.0194x; 1.0194x over previous
#include <cuda_runtime.h>

// C[b,g] = softor_s( softand_l( x[b, I[g,s,l]] ) ),  gamma = 1e-3
// B=64, G=2048, S=32, L=8
//
// Scaled domain: w = -x * KINV  (KINV = 1/(gamma*ln2))
//   softand':  mW = max_l w,  sum = sum_l exp2(w_l - mW),  aw = mW + lg2(sum)
//   softor' :  Mw = min_s aw,  S = sum_s exp2(Mw - aw_s)
//              C  = (lg2(S) - Mw) * gamma*ln2
//
// Layout: one 256-thread block per g. Warp w, pass p, half-warp h handles
// s = p*16 + w*2 + h; lane owns 4 consecutive b via LDG.128 (16 lanes x 16B
// = full 64-b row slice, coalesced). Softand results go to smem aw[s][b];
// a 64-thread epilogue does the exact softor per b.

#define NB 64
#define NG 2048
#define NS 32
#define NL 8
#define NTHR 256
#define AWSTRIDE 68   // floats per aw row: 16B-aligned, bank-stride 4

#define KINV 1442.6950408889634f
#define GLN2 0.0006931471805599453f

typedef unsigned long long u64;

// Transposed, negated, scaled x: w[g][b] = -x[b][g] * KINV.
__device__ float g_w[NG * NB];

// Tiled transpose 64x2048 -> 2048x64, coalesced both sides; fuses -x*KINV.
__global__ void transpose_kernel(const float* __restrict__ x) {
    __shared__ float tile[32][33];
    const int gx = blockIdx.x * 32;
    const int bx = blockIdx.y * 32;
    const int tx = threadIdx.x;
    const int ty = threadIdx.y;
#pragma unroll
    for (int i = 0; i < 32; i += 8)
        tile[ty + i][tx] = x[(bx + ty + i) * NG + gx + tx] * (-KINV);
    __syncthreads();
#pragma unroll
    for (int i = 0; i < 32; i += 8)
        g_w[(gx + ty + i) * NB + bx + tx] = tile[tx][ty + i];
#if __CUDA_ARCH__ >= 900
    // Trigger AFTER the g_w stores (those writes must be visible to the
    // dependent grid at its cudaGridDependencySynchronize).
    cudaTriggerProgrammaticLaunchCompletion();
#endif
}

__device__ __forceinline__ float ex2_approx(float t) {
    float r;
    asm("ex2.approx.ftz.f32 %0, %1;" : "=f"(r) : "f"(t));
    return r;
}
__device__ __forceinline__ float lg2_approx(float t) {
    float r;
    asm("lg2.approx.f32 %0, %1;" : "=f"(r) : "f"(t));
    return r;
}

// ---- packed f32x2 helpers (sm_100+: add/sub/mul/fma only) ----
__device__ __forceinline__ u64 fadd2(u64 a, u64 b) {
    u64 r; asm("add.rn.f32x2 %0, %1, %2;" : "=l"(r) : "l"(a), "l"(b)); return r;
}
__device__ __forceinline__ u64 ffma2(u64 a, u64 b, u64 c) {
    u64 r; asm("fma.rn.f32x2 %0, %1, %2, %3;" : "=l"(r) : "l"(a), "l"(b), "l"(c));
    return r;
}
__device__ __forceinline__ void unpack2(u64 t, float& lo, float& hi) {
    asm("mov.b64 {%0, %1}, %2;" : "=f"(lo), "=f"(hi) : "l"(t));
}
__device__ __forceinline__ u64 pack2(float lo, float hi) {
    u64 r; asm("mov.b64 %0, {%1, %2};" : "=l"(r) : "f"(lo), "f"(hi)); return r;
}
__device__ __forceinline__ u64 ex2pair(u64 t) {
    float lo, hi;
    unpack2(t, lo, hi);
    return pack2(ex2_approx(lo), ex2_approx(hi));
}

__global__ __launch_bounds__(NTHR) void clause_kernel(
    const int* __restrict__ I,  // [NG, NS, NL] int32
    float* __restrict__ out)    // [NB, NG]
{
    const int g = blockIdx.x;
    const int tid = threadIdx.x;
    const int lane = tid & 31;
    const int wid = tid >> 5;
    const int half = lane >> 4;   // which of 2 s this half-warp handles
    const int hb = lane & 15;     // 4*hb = first owned b

    __shared__ int soff[NS * NL];             // pre-shifted byte offsets
    __shared__ float s_aw[NS * AWSTRIDE];     // softand results aw[s][b]

    // Prologue: independent of g_w — overlaps with the transpose under PDL.
    if (tid < NS * NL / 4) {
        int4 r = ((const int4*)(I + g * (NS * NL)))[tid];
        r.x = (r.x & (NG - 1)) << 8;   // *256 bytes = row stride in bytes
        r.y = (r.y & (NG - 1)) << 8;
        r.z = (r.z & (NG - 1)) << 8;
        r.w = (r.w & (NG - 1)) << 8;
        ((int4*)soff)[tid] = r;
    }
    __syncthreads();

#if __CUDA_ARCH__ >= 900
    cudaGridDependencySynchronize();
#endif

    const char* base = (const char*)g_w + hb * 16;  // lane's 16B column slice
    const u64 NEG1x2 = 0xBF800000BF800000ull;       // packed (-1.0f, -1.0f)

#pragma unroll
    for (int p = 0; p < 2; p++) {
        const int s = p * 16 + wid * 2 + half;
        const int4* so4 = (const int4*)(soff + s * NL);
        const int4 oA = so4[0];
        const int4 oB = so4[1];

        ulonglong2 q0 = *(const ulonglong2*)(base + oA.x);
        ulonglong2 q1 = *(const ulonglong2*)(base + oA.y);
        ulonglong2 q2 = *(const ulonglong2*)(base + oA.z);
        ulonglong2 q3 = *(const ulonglong2*)(base + oA.w);
        ulonglong2 q4 = *(const ulonglong2*)(base + oB.x);
        ulonglong2 q5 = *(const ulonglong2*)(base + oB.y);
        ulonglong2 q6 = *(const ulonglong2*)(base + oB.z);
        ulonglong2 q7 = *(const ulonglong2*)(base + oB.w);

        // Scalar views for the max trees (mov.b64 unpacks alias registers).
        float a0, b0, c0, d0, a1, b1, c1, d1, a2, b2, c2, d2, a3, b3, c3, d3;
        float a4, b4, c4, d4, a5, b5, c5, d5, a6, b6, c6, d6, a7, b7, c7, d7;
        unpack2(q0.x, a0, b0); unpack2(q0.y, c0, d0);
        unpack2(q1.x, a1, b1); unpack2(q1.y, c1, d1);
        unpack2(q2.x, a2, b2); unpack2(q2.y, c2, d2);
        unpack2(q3.x, a3, b3); unpack2(q3.y, c3, d3);
        unpack2(q4.x, a4, b4); unpack2(q4.y, c4, d4);
        unpack2(q5.x, a5, b5); unpack2(q5.y, c5, d5);
        unpack2(q6.x, a6, b6); unpack2(q6.y, c6, d6);
        unpack2(q7.x, a7, b7); unpack2(q7.y, c7, d7);

        float ma = fmaxf(fmaxf(fmaxf(a0, a1), fmaxf(a2, a3)),
                         fmaxf(fmaxf(a4, a5), fmaxf(a6, a7)));
        float mb = fmaxf(fmaxf(fmaxf(b0, b1), fmaxf(b2, b3)),
                         fmaxf(fmaxf(b4, b5), fmaxf(b6, b7)));
        float mc = fmaxf(fmaxf(fmaxf(c0, c1), fmaxf(c2, c3)),
                         fmaxf(fmaxf(c4, c5), fmaxf(c6, c7)));
        float md = fmaxf(fmaxf(fmaxf(d0, d1), fmaxf(d2, d3)),
                         fmaxf(fmaxf(d4, d5), fmaxf(d6, d7)));
        u64 mlo = pack2(ma, mb);
        u64 mhi = pack2(mc, md);

        // Packed diffs (fma(m,-1,w) == w-m bitwise), MUFU ex2, packed sums.
        u64 slo = fadd2(
            fadd2(fadd2(ex2pair(ffma2(mlo, NEG1x2, q0.x)),
                        ex2pair(ffma2(mlo, NEG1x2, q1.x))),
                  fadd2(ex2pair(ffma2(mlo, NEG1x2, q2.x)),
                        ex2pair(ffma2(mlo, NEG1x2, q3.x)))),
            fadd2(fadd2(ex2pair(ffma2(mlo, NEG1x2, q4.x)),
                        ex2pair(ffma2(mlo, NEG1x2, q5.x))),
                  fadd2(ex2pair(ffma2(mlo, NEG1x2, q6.x)),
                        ex2pair(ffma2(mlo, NEG1x2, q7.x)))));
        u64 shi = fadd2(
            fadd2(fadd2(ex2pair(ffma2(mhi, NEG1x2, q0.y)),
                        ex2pair(ffma2(mhi, NEG1x2, q1.y))),
                  fadd2(ex2pair(ffma2(mhi, NEG1x2, q2.y)),
                        ex2pair(ffma2(mhi, NEG1x2, q3.y)))),
            fadd2(fadd2(ex2pair(ffma2(mhi, NEG1x2, q4.y)),
                        ex2pair(ffma2(mhi, NEG1x2, q5.y))),
                  fadd2(ex2pair(ffma2(mhi, NEG1x2, q6.y)),
                        ex2pair(ffma2(mhi, NEG1x2, q7.y)))));

        float sa, sb, sc, sd;
        unpack2(slo, sa, sb);
        unpack2(shi, sc, sd);

        float4 awv;
        awv.x = ma + lg2_approx(sa);
        awv.y = mb + lg2_approx(sb);
        awv.z = mc + lg2_approx(sc);
        awv.w = md + lg2_approx(sd);
        *(float4*)&s_aw[s * AWSTRIDE + hb * 4] = awv;
    }
    __syncthreads();

    // Epilogue: 64 threads, one b each — exact softor over all 32 s.
    if (tid < NB) {
        const int b = tid;
        float aw[NS];
#pragma unroll
        for (int s = 0; s < NS; s++) aw[s] = s_aw[s * AWSTRIDE + b];

        float Mw = aw[0];
#pragma unroll
        for (int s = 1; s < NS; s++) Mw = fminf(Mw, aw[s]);
        float S = 0.0f;
#pragma unroll
        for (int s = 0; s < NS; s++) S += ex2_approx(Mw - aw[s]);

        out[b * NG + g] = (lg2_approx(S) - Mw) * GLN2;
    }
}

extern "C" void kernel_launch(void* const* d_in, const int* in_sizes, int n_in,
                              void* d_out, int out_size) {
    // Identify inputs by element count:
    //   x:  64*2048   = 131072 float32
    //   I:  2048*32*8 = 524288 int32
    const float* x = nullptr;
    const int* I = nullptr;
    for (int i = 0; i < n_in; i++) {
        if (in_sizes[i] == NB * NG)           x = (const float*)d_in[i];
        else if (in_sizes[i] == NG * NS * NL) I = (const int*)d_in[i];
    }

    float* out = (float*)d_out;  // [64, 2048] fp32

    dim3 tgrid(NG / 32, NB / 32);
    dim3 tblock(32, 8);
    transpose_kernel<<<tgrid, tblock>>>(x);

    // PDL: clause_kernel launches early; gates on transpose completion
    // (trigger placed after the g_w stores) before touching g_w.
    cudaLaunchConfig_t cfg = {};
    cfg.gridDim = dim3(NG);
    cfg.blockDim = dim3(NTHR);
    cfg.dynamicSmemBytes = 0;
    cfg.stream = 0;
    cudaLaunchAttribute attr[1];
    attr[0].id = cudaLaunchAttributeProgrammaticStreamSerialization;
    attr[0].val.programmaticStreamSerializationAllowed = 1;
    cfg.attrs = attr;
    cfg.numAttrs = 1;
    cudaLaunchKernelEx(&cfg, clause_kernel, I, (float*)d_out);
}